// round 13
// baseline (speedup 1.0000x reference)
#include <cuda_runtime.h>
#include <cstdint>

#define PES 15
#define DIN 18

// ---- shared memory layout (float indices) ----
#define W1_OFF   0            // W1 B-frag PAIRED: 4 kk * 8 ntp * 128 = 4096 (16KB)
#define W2_OFF   4096         // W2 B-frag PAIRED: 16 kk * 8 ntp * 128 = 16384 (64KB)
#define B1_OFF   20480        // 128
#define B2_OFF   20608        // 128
#define W3_OFF   20736        // 384
#define B3_OFF   21120        // 4
#define PX_OFF   21124        // 256*3 = 768
#define SC_OFF   21892        // scratch union: XA (8192) then A2 (32768) overlay
#define SMEM_FLOATS (21892 + 32768)
#define SMEM_BYTES  (SMEM_FLOATS * 4)    // 218640 B = 213.5 KB

__device__ __forceinline__ uint32_t f2tf32(float x) {
    uint32_t r;
    asm("cvt.rna.tf32.f32 %0, %1;" : "=r"(r) : "f"(x));
    return r;
}

// D += A(16x8) * B(8x8), tf32 operands, f32 accum
__device__ __forceinline__ void mma8(float* d, const uint32_t* a, const uint32_t* b) {
    asm volatile("mma.sync.aligned.m16n8k8.row.col.f32.tf32.tf32.f32 "
                 "{%0,%1,%2,%3}, {%4,%5,%6,%7}, {%8,%9}, {%0,%1,%2,%3};"
                 : "+f"(d[0]), "+f"(d[1]), "+f"(d[2]), "+f"(d[3])
                 : "r"(a[0]), "r"(a[1]), "r"(a[2]), "r"(a[3]),
                   "r"(b[0]), "r"(b[1]));
}

__global__ __launch_bounds__(256, 1)
void nsc_m32s_kernel(const float* __restrict__ points,
                     const float* __restrict__ enc,
                     const float* __restrict__ W1, const float* __restrict__ b1,
                     const float* __restrict__ W2, const float* __restrict__ b2,
                     const float* __restrict__ W3, const float* __restrict__ b3,
                     const int* __restrict__ complexes,
                     float* __restrict__ out, int C, long long lipIdx)
{
    extern __shared__ float sm[];
    uint32_t* smu = (uint32_t*)sm;

    const int tid  = threadIdx.x;
    const int lane = tid & 31;
    const int wcta = tid >> 5;        // warp id; owns rows [wcta*32, wcta*32+32)

    // ============ stage weights ONCE (persistent CTA) ============
    // PAIRED B-frag layout: pairblk = kk*8 + ntp covers nt = 2*ntp, 2*ntp+1.
    // slot = pairblk*128 + ln*4 + sub; sub 0,1 = regs of nt_even; 2,3 = nt_odd.
    // value = W[n][k], n = nt*8 + ln/4, k = kk*8 + (ln&3) + 4*reg.
    for (int idx = tid; idx < 4096; idx += 256) {            // W1 (4 kk * 8 ntp)
        int pb = idx >> 7, r = idx & 127;
        int ln = r >> 2, sub = r & 3;
        int kk = pb >> 3, ntp = pb & 7;
        int nt = ntp * 2 + (sub >> 1), rg = sub & 1;
        int n = nt * 8 + (ln >> 2), k = kk * 8 + (ln & 3) + 4 * rg;
        float v = (k < DIN) ? __ldg(&W1[n * DIN + k]) : 0.f;
        smu[W1_OFF + idx] = f2tf32(v);
    }
    for (int idx = tid; idx < 16384; idx += 256) {           // W2 (16 kk * 8 ntp)
        int pb = idx >> 7, r = idx & 127;
        int ln = r >> 2, sub = r & 3;
        int kk = pb >> 3, ntp = pb & 7;
        int nt = ntp * 2 + (sub >> 1), rg = sub & 1;
        int n = nt * 8 + (ln >> 2), k = kk * 8 + (ln & 3) + 4 * rg;
        smu[W2_OFF + idx] = f2tf32(__ldg(&W2[n * 128 + k]));
    }
    if (tid < 128) { sm[B1_OFF + tid] = b1[tid]; sm[B2_OFF + tid] = b2[tid]; }
    for (int idx = tid; idx < 384; idx += 256) sm[W3_OFF + idx] = W3[idx];
    if (tid < 3) sm[B3_OFF + tid] = b3[tid];

    if (blockIdx.x == 0 && tid == 0) out[lipIdx] = 1.0f;

    const int src1 = (lane & ~3) | ((lane & 3) >> 1);
    const int src2 = src1 + 2;
    const bool par = (lane & 1) != 0;
    const long long xoff = (long long)C * 256 * 3;

    // ============ persistent loop: 1 tile = 1 full complex (256 rows) ============
    for (int c = blockIdx.x; c < C; c += gridDim.x) {
        __syncthreads();   // previous tile fully consumed (incl. a2 reads)

        // ---- features: thread t -> row t (0..255) ----
        {
            int v4[4];
            #pragma unroll
            for (int q = 0; q < 4; q++) v4[q] = complexes[c * 4 + q];

            const int gi = tid >> 4, gj = tid & 15;
            const float inv = 1.0f / 15.0f;
            const float u = gi * inv, w = gj * inv;
            float wt[4];
            wt[0] = (1.f - u) * (1.f - w); wt[1] = (1.f - u) * w;
            wt[2] = u * (1.f - w);         wt[3] = u * w;

            float xf[32];
            #pragma unroll
            for (int f = 0; f < PES; f++) {
                float s = 0.f;
                #pragma unroll
                for (int q = 0; q < 4; q++) s += wt[q] * __ldg(&enc[(long long)v4[q] * PES + f]);
                xf[f] = s;
            }
            #pragma unroll
            for (int f = 0; f < 3; f++) {
                float s = 0.f;
                #pragma unroll
                for (int q = 0; q < 4; q++) s += wt[q] * __ldg(&points[(long long)v4[q] * 3 + f]);
                sm[PX_OFF + tid * 3 + f] = s;
                xf[PES + f] = __sinf(s);
            }
            #pragma unroll
            for (int f = DIN; f < 32; f++) xf[f] = 0.f;

            // scatter into XA A-frag layout: block (tid>>4)*4+kk (blocks 0..63)
            const int r16  = tid & 15;
            const int base = SC_OFF + (tid >> 4) * 512 + ((r16 & 7) * 4) * 4 + (r16 >> 3);
            #pragma unroll
            for (int col = 0; col < 32; col++) {
                int kk = col >> 3, c8 = col & 7;
                smu[base + kk * 128 + (c8 & 3) * 4 + ((c8 >> 2) << 1)] = f2tf32(xf[col]);
            }
        }
        __syncthreads();

        // ---- hoist layer-1 A-frags, then free the XA region for a2 ----
        uint4 av[2][4];
        #pragma unroll
        for (int mt = 0; mt < 2; mt++)
            #pragma unroll
            for (int kk = 0; kk < 4; kk++)
                av[mt][kk] = *(const uint4*)&smu[SC_OFF + ((wcta * 2 + mt) * 4 + kk) * 128 + lane * 4];
        __syncthreads();   // all av loaded before a2 overwrites the region

        // ---- layer 1 (nt-outer) + sin + permute -> a2 in smem ----
        // a2 block = wcta*32 + mt*16 + nt (blocks 0..255)
        #pragma unroll
        for (int ntp = 0; ntp < 8; ntp++) {
            float hh[2][2][4];
            #pragma unroll
            for (int mt = 0; mt < 2; mt++)
                #pragma unroll
                for (int s = 0; s < 2; s++)
                    #pragma unroll
                    for (int r = 0; r < 4; r++) hh[mt][s][r] = 0.f;

            #pragma unroll
            for (int kk = 0; kk < 4; kk++) {
                uint4 bv = *(const uint4*)&smu[W1_OFF + (kk * 8 + ntp) * 128 + lane * 4];
                mma8(hh[0][0], (const uint32_t*)&av[0][kk], &bv.x);
                mma8(hh[0][1], (const uint32_t*)&av[0][kk], &bv.z);
                mma8(hh[1][0], (const uint32_t*)&av[1][kk], &bv.x);
                mma8(hh[1][1], (const uint32_t*)&av[1][kk], &bv.z);
            }

            #pragma unroll
            for (int s = 0; s < 2; s++) {
                int nt = ntp * 2 + s;
                float2 bb = *(const float2*)&sm[B1_OFF + nt * 8 + 2 * (lane & 3)];
                #pragma unroll
                for (int mt = 0; mt < 2; mt++) {
                    float s0 = __uint_as_float(f2tf32(__sinf(hh[mt][s][0] + bb.x)));
                    float s1 = __uint_as_float(f2tf32(__sinf(hh[mt][s][1] + bb.y)));
                    float s2 = __uint_as_float(f2tf32(__sinf(hh[mt][s][2] + bb.x)));
                    float s3 = __uint_as_float(f2tf32(__sinf(hh[mt][s][3] + bb.y)));
                    float t0 = __shfl_sync(0xffffffffu, s0, src1);
                    float t1 = __shfl_sync(0xffffffffu, s1, src1);
                    float t2 = __shfl_sync(0xffffffffu, s2, src1);
                    float t3 = __shfl_sync(0xffffffffu, s3, src1);
                    float u0 = __shfl_sync(0xffffffffu, s0, src2);
                    float u1 = __shfl_sync(0xffffffffu, s1, src2);
                    float u2 = __shfl_sync(0xffffffffu, s2, src2);
                    float u3 = __shfl_sync(0xffffffffu, s3, src2);
                    uint4 fr;
                    fr.x = __float_as_uint(par ? t1 : t0);
                    fr.y = __float_as_uint(par ? t3 : t2);
                    fr.z = __float_as_uint(par ? u1 : u0);
                    fr.w = __float_as_uint(par ? u3 : u2);
                    *(uint4*)&smu[SC_OFF + (wcta * 32 + mt * 16 + nt) * 128 + lane * 4] = fr;
                }
            }
        }
        __syncwarp();      // warp-private a2 region: order STS before LDS

        // ---- layer 2 (2 N-passes) + fused layer 3; A from smem a2 ----
        float p3[2][2][3];
        #pragma unroll
        for (int mt = 0; mt < 2; mt++)
            #pragma unroll
            for (int rh = 0; rh < 2; rh++)
                #pragma unroll
                for (int f = 0; f < 3; f++) p3[mt][rh][f] = 0.f;

        #pragma unroll
        for (int pass = 0; pass < 2; pass++) {
            float acc[2][8][4];          // 64 regs
            #pragma unroll
            for (int mt = 0; mt < 2; mt++)
                #pragma unroll
                for (int nt = 0; nt < 8; nt++)
                    #pragma unroll
                    for (int r = 0; r < 4; r++) acc[mt][nt][r] = 0.f;

            #pragma unroll
            for (int kk = 0; kk < 16; kk++) {
                uint4 a0 = *(const uint4*)&smu[SC_OFF + (wcta * 32 + kk) * 128 + lane * 4];
                uint4 a1 = *(const uint4*)&smu[SC_OFF + (wcta * 32 + 16 + kk) * 128 + lane * 4];
                #pragma unroll
                for (int ntpl = 0; ntpl < 4; ntpl++) {
                    int ntp = pass * 4 + ntpl;
                    uint4 bv = *(const uint4*)&smu[W2_OFF + (kk * 8 + ntp) * 128 + lane * 4];
                    mma8(acc[0][2 * ntpl + 0], (const uint32_t*)&a0, &bv.x);
                    mma8(acc[0][2 * ntpl + 1], (const uint32_t*)&a0, &bv.z);
                    mma8(acc[1][2 * ntpl + 0], (const uint32_t*)&a1, &bv.x);
                    mma8(acc[1][2 * ntpl + 1], (const uint32_t*)&a1, &bv.z);
                }
            }

            // epilogue: sin(D2 + b2), accumulate layer-3 partials
            #pragma unroll
            for (int ntl = 0; ntl < 8; ntl++) {
                int nt = pass * 8 + ntl;
                float2 bb = *(const float2*)&sm[B2_OFF + nt * 8 + 2 * (lane & 3)];
                #pragma unroll
                for (int mt = 0; mt < 2; mt++) {
                    float h0 = __sinf(acc[mt][ntl][0] + bb.x);
                    float h1v = __sinf(acc[mt][ntl][1] + bb.y);
                    float h2v = __sinf(acc[mt][ntl][2] + bb.x);
                    float h3 = __sinf(acc[mt][ntl][3] + bb.y);
                    #pragma unroll
                    for (int f = 0; f < 3; f++) {
                        float2 wv = *(const float2*)&sm[W3_OFF + f * 128 + nt * 8 + 2 * (lane & 3)];
                        p3[mt][0][f] += h0 * wv.x + h1v * wv.y;
                        p3[mt][1][f] += h2v * wv.x + h3 * wv.y;
                    }
                }
            }
        }

        // reduce layer-3 partials across each quad
        #pragma unroll
        for (int mt = 0; mt < 2; mt++)
            #pragma unroll
            for (int rh = 0; rh < 2; rh++)
                #pragma unroll
                for (int f = 0; f < 3; f++) {
                    float v = p3[mt][rh][f];
                    v += __shfl_xor_sync(0xffffffffu, v, 1);
                    v += __shfl_xor_sync(0xffffffffu, v, 2);
                    p3[mt][rh][f] = v;
                }

        if ((lane & 3) == 0) {
            const int q = lane >> 2;
            #pragma unroll
            for (int mt = 0; mt < 2; mt++)
                #pragma unroll
                for (int rh = 0; rh < 2; rh++) {
                    int row = wcta * 32 + mt * 16 + rh * 8 + q;   // 0..255
                    long long g = (long long)c * 256 + row;
                    #pragma unroll
                    for (int f = 0; f < 3; f++) {
                        float o = p3[mt][rh][f] + sm[B3_OFF + f];
                        out[g * 3 + f]        = sm[PX_OFF + row * 3 + f] + o;
                        out[xoff + g * 3 + f] = o;
                    }
                }
        }
    }
}

extern "C" void kernel_launch(void* const* d_in, const int* in_sizes, int n_in,
                              void* d_out, int out_size) {
    const float* points    = (const float*)d_in[0];
    const float* enc       = (const float*)d_in[1];
    const float* W1        = (const float*)d_in[2];
    const float* b1        = (const float*)d_in[3];
    const float* W2        = (const float*)d_in[4];
    const float* b2        = (const float*)d_in[5];
    const float* W3        = (const float*)d_in[6];
    const float* b3        = (const float*)d_in[7];
    const int*   complexes = (const int*)d_in[8];   // JAX int64 -> int32 (x64 disabled)

    const int C = in_sizes[8] / 4;
    float* out = (float*)d_out;

    int grid = 148;                    // persistent: 1 CTA per SM on B200
    if (grid > C) grid = C;

    cudaFuncSetAttribute(nsc_m32s_kernel,
                         cudaFuncAttributeMaxDynamicSharedMemorySize, SMEM_BYTES);
    nsc_m32s_kernel<<<grid, 256, SMEM_BYTES>>>(points, enc, W1, b1, W2, b2, W3, b3,
                                               complexes, out, C,
                                               (long long)out_size - 1);
}

// round 16
// speedup vs baseline: 1.0311x; 1.0311x over previous
#include <cuda_runtime.h>
#include <cstdint>

#define PES 15
#define DIN 18

// ---- shared memory layout (float indices) ----
#define W1_OFF   0        // W1 B-frag PAIRED, K=24 (b1 folded at k=18): 3kk*8ntp*128 = 3072 (12KB)
#define W2_OFF   3072     // W2 B-frag PAIRED: 16kk*8ntp*128 = 16384 (64KB)
#define B2_OFF   19456    // 128
#define PB_OFF   19584    // layer-3 partials: 64 rows * 4 nb * 3 = 768
#define A2_OFF   20352    // a2 frags: 4 mt * 16 kk * 128 = 8192 (32KB)
#define SMEM_FLOATS 28544
#define SMEM_BYTES (SMEM_FLOATS * 4)   // 111.5 KB -> 2 CTAs/SM

__device__ __forceinline__ uint32_t f2tf32(float x) {
    uint32_t r;
    asm("cvt.rna.tf32.f32 %0, %1;" : "=r"(r) : "f"(x));
    return r;
}

// D += A(16x8) * B(8x8), tf32 operands, f32 accum
__device__ __forceinline__ void mma8(float* d, const uint32_t* a, const uint32_t* b) {
    asm volatile("mma.sync.aligned.m16n8k8.row.col.f32.tf32.tf32.f32 "
                 "{%0,%1,%2,%3}, {%4,%5,%6,%7}, {%8,%9}, {%0,%1,%2,%3};"
                 : "+f"(d[0]), "+f"(d[1]), "+f"(d[2]), "+f"(d[3])
                 : "r"(a[0]), "r"(a[1]), "r"(a[2]), "r"(a[3]),
                   "r"(b[0]), "r"(b[1]));
}

__global__ __launch_bounds__(256, 2)
void nsc_sq_kernel(const float* __restrict__ points,
                   const float* __restrict__ enc,
                   const float* __restrict__ W1, const float* __restrict__ b1,
                   const float* __restrict__ W2, const float* __restrict__ b2,
                   const float* __restrict__ W3, const float* __restrict__ b3,
                   const int* __restrict__ complexes,
                   float* __restrict__ out, int C, long long lipIdx)
{
    extern __shared__ float sm[];
    uint32_t* smu = (uint32_t*)sm;

    const int tid  = threadIdx.x;
    const int lane = tid & 31;
    const int w    = tid >> 5;

    // layer-1 task: mt-block mw (16 rows), n-half nh (8 nt)
    const int mw = w >> 1, nh = w & 1;
    // layer-2 task: m2 (32 rows = 2 m-tiles), nb (32 cols = 4 nt = 2 pairblocks)
    const int m2 = w >> 2, nb = w & 3;

    // ============ stage weights ONCE ============
    // PAIRED B-frag: pairblk = kk*8+ntp covers nt=2*ntp,2*ntp+1;
    // slot = pairblk*128 + ln*4 + sub; n = nt*8+ln/4, k = kk*8+(ln&3)+4*rg.
    for (int idx = tid; idx < 3072; idx += 256) {            // W1: K=24, b1 at k=18
        int pb = idx >> 7, r = idx & 127;
        int ln = r >> 2, sub = r & 3;
        int kk = pb >> 3, ntp = pb & 7;
        int nt = ntp * 2 + (sub >> 1), rg = sub & 1;
        int n = nt * 8 + (ln >> 2), k = kk * 8 + (ln & 3) + 4 * rg;
        float v = (k < DIN) ? __ldg(&W1[n * DIN + k]) : (k == DIN ? __ldg(&b1[n]) : 0.f);
        smu[W1_OFF + idx] = f2tf32(v);
    }
    for (int idx = tid; idx < 16384; idx += 256) {           // W2
        int pb = idx >> 7, r = idx & 127;
        int ln = r >> 2, sub = r & 3;
        int kk = pb >> 3, ntp = pb & 7;
        int nt = ntp * 2 + (sub >> 1), rg = sub & 1;
        int n = nt * 8 + (ln >> 2), k = kk * 8 + (ln & 3) + 4 * rg;
        smu[W2_OFF + idx] = f2tf32(__ldg(&W2[n * 128 + k]));
    }
    if (tid < 128) sm[B2_OFF + tid] = b2[tid];
    if (blockIdx.x == 0 && tid == 0) out[lipIdx] = 1.0f;

    const int src1 = (lane & ~3) | ((lane & 3) >> 1);
    const int src2 = src1 + 2;
    const bool par = (lane & 1) != 0;
    const long long xoff = (long long)C * 256 * 3;
    const float inv = 1.0f / 15.0f;
    const int total = 4 * C;

    // ============ persistent loop: 1 tile = 64 rows (quarter complex) ============
    for (int b = blockIdx.x; b < total; b += gridDim.x) {
        const int c  = b >> 2;
        const int qd = b & 3;

        __syncthreads();   // previous tile's a2/pbuf fully consumed

        int v4[4];
        #pragma unroll
        for (int q = 0; q < 4; q++) v4[q] = complexes[c * 4 + q];

        // ---- finalizer's p (registers, thread t<64 <-> local row t) ----
        float px0 = 0.f, px1 = 0.f, px2 = 0.f;
        if (tid < 64) {
            int p_idx = qd * 64 + tid;
            float u = (p_idx >> 4) * inv, ww = (p_idx & 15) * inv;
            float wt[4] = { (1.f-u)*(1.f-ww), (1.f-u)*ww, u*(1.f-ww), u*ww };
            #pragma unroll
            for (int q = 0; q < 4; q++) {
                const float* pp = points + (long long)v4[q] * 3;
                px0 += wt[q] * __ldg(pp);
                px1 += wt[q] * __ldg(pp + 1);
                px2 += wt[q] * __ldg(pp + 2);
            }
        }

        // ---- build layer-1 A-frags directly (no XA staging) ----
        // frag value (lane,reg rr): row = mw*16 + (lane>>2) + 8*(rr&1),
        //                           col = kk*8 + (lane&3) + 4*(rr>>1)
        uint32_t av[3][4];
        {
            int r0 = mw * 16 + (lane >> 2);
            float wtr[2][4];
            #pragma unroll
            for (int h = 0; h < 2; h++) {
                int p_idx = qd * 64 + r0 + 8 * h;
                float u = (p_idx >> 4) * inv, ww = (p_idx & 15) * inv;
                wtr[h][0] = (1.f-u)*(1.f-ww); wtr[h][1] = (1.f-u)*ww;
                wtr[h][2] = u*(1.f-ww);       wtr[h][3] = u*ww;
            }
            #pragma unroll
            for (int kk = 0; kk < 3; kk++) {
                #pragma unroll
                for (int rr = 0; rr < 4; rr++) {
                    int col = kk * 8 + (lane & 3) + 4 * (rr >> 1);
                    const float* wt = wtr[rr & 1];
                    float val;
                    if (col < PES) {
                        val = 0.f;
                        #pragma unroll
                        for (int q = 0; q < 4; q++)
                            val += wt[q] * __ldg(&enc[(long long)v4[q] * PES + col]);
                    } else if (col < DIN) {
                        float s = 0.f;
                        #pragma unroll
                        for (int q = 0; q < 4; q++)
                            s += wt[q] * __ldg(&points[(long long)v4[q] * 3 + (col - PES)]);
                        val = __sinf(s);
                    } else if (col == DIN) {
                        val = 1.0f;           // ones column -> b1 via W1 row k=18
                    } else {
                        val = 0.f;
                    }
                    av[kk][rr] = f2tf32(val);
                }
            }
        }

        // ---- layer 1 (nt-outer) + sin + permute -> a2 in smem ----
        #pragma unroll
        for (int ntp = 0; ntp < 4; ntp++) {
            float hh[2][4];
            #pragma unroll
            for (int s = 0; s < 2; s++)
                #pragma unroll
                for (int r = 0; r < 4; r++) hh[s][r] = 0.f;

            #pragma unroll
            for (int kk = 0; kk < 3; kk++) {
                uint4 bv = *(const uint4*)&smu[W1_OFF + (kk * 8 + nh * 4 + ntp) * 128 + lane * 4];
                mma8(hh[0], av[kk], &bv.x);
                mma8(hh[1], av[kk], &bv.z);
            }

            #pragma unroll
            for (int s = 0; s < 2; s++) {
                int nt = nh * 8 + ntp * 2 + s;
                float s0 = __uint_as_float(f2tf32(__sinf(hh[s][0])));
                float s1 = __uint_as_float(f2tf32(__sinf(hh[s][1])));
                float s2 = __uint_as_float(f2tf32(__sinf(hh[s][2])));
                float s3 = __uint_as_float(f2tf32(__sinf(hh[s][3])));
                float t0 = __shfl_sync(0xffffffffu, s0, src1);
                float t1 = __shfl_sync(0xffffffffu, s1, src1);
                float t2 = __shfl_sync(0xffffffffu, s2, src1);
                float t3 = __shfl_sync(0xffffffffu, s3, src1);
                float u0 = __shfl_sync(0xffffffffu, s0, src2);
                float u1 = __shfl_sync(0xffffffffu, s1, src2);
                float u2 = __shfl_sync(0xffffffffu, s2, src2);
                float u3 = __shfl_sync(0xffffffffu, s3, src2);
                uint4 fr;
                fr.x = __float_as_uint(par ? t1 : t0);
                fr.y = __float_as_uint(par ? t3 : t2);
                fr.z = __float_as_uint(par ? u1 : u0);
                fr.w = __float_as_uint(par ? u3 : u2);
                *(uint4*)&smu[A2_OFF + (mw * 16 + nt) * 128 + lane * 4] = fr;
            }
        }
        __syncthreads();   // a2 complete (cross-warp consumption)

        // ---- layer 2: 32x32 warp tile ----
        float acc[2][4][4];
        #pragma unroll
        for (int mt = 0; mt < 2; mt++)
            #pragma unroll
            for (int nt = 0; nt < 4; nt++)
                #pragma unroll
                for (int r = 0; r < 4; r++) acc[mt][nt][r] = 0.f;

        #pragma unroll
        for (int kk = 0; kk < 16; kk++) {
            uint4 a0 = *(const uint4*)&smu[A2_OFF + ((m2 * 2 + 0) * 16 + kk) * 128 + lane * 4];
            uint4 a1 = *(const uint4*)&smu[A2_OFF + ((m2 * 2 + 1) * 16 + kk) * 128 + lane * 4];
            uint4 bv0 = *(const uint4*)&smu[W2_OFF + (kk * 8 + nb * 2 + 0) * 128 + lane * 4];
            uint4 bv1 = *(const uint4*)&smu[W2_OFF + (kk * 8 + nb * 2 + 1) * 128 + lane * 4];
            mma8(acc[0][0], (const uint32_t*)&a0, &bv0.x);
            mma8(acc[0][1], (const uint32_t*)&a0, &bv0.z);
            mma8(acc[0][2], (const uint32_t*)&a0, &bv1.x);
            mma8(acc[0][3], (const uint32_t*)&a0, &bv1.z);
            mma8(acc[1][0], (const uint32_t*)&a1, &bv0.x);
            mma8(acc[1][1], (const uint32_t*)&a1, &bv0.z);
            mma8(acc[1][2], (const uint32_t*)&a1, &bv1.x);
            mma8(acc[1][3], (const uint32_t*)&a1, &bv1.z);
        }

        // ---- epilogue: sin(D2+b2), layer-3 partials over this warp's 32 cols ----
        float p3[2][2][3];
        #pragma unroll
        for (int mt = 0; mt < 2; mt++)
            #pragma unroll
            for (int rh = 0; rh < 2; rh++)
                #pragma unroll
                for (int f = 0; f < 3; f++) p3[mt][rh][f] = 0.f;

        #pragma unroll
        for (int ntl = 0; ntl < 4; ntl++) {
            int col0 = (nb * 4 + ntl) * 8 + 2 * (lane & 3);
            float2 bb = *(const float2*)&sm[B2_OFF + col0];
            float2 wv0 = __ldg((const float2*)(W3 + 0 * 128 + col0));
            float2 wv1 = __ldg((const float2*)(W3 + 1 * 128 + col0));
            float2 wv2 = __ldg((const float2*)(W3 + 2 * 128 + col0));
            #pragma unroll
            for (int mt = 0; mt < 2; mt++) {
                float h0 = __sinf(acc[mt][ntl][0] + bb.x);
                float h1 = __sinf(acc[mt][ntl][1] + bb.y);
                float h2 = __sinf(acc[mt][ntl][2] + bb.x);
                float h3 = __sinf(acc[mt][ntl][3] + bb.y);
                p3[mt][0][0] += h0 * wv0.x + h1 * wv0.y;
                p3[mt][0][1] += h0 * wv1.x + h1 * wv1.y;
                p3[mt][0][2] += h0 * wv2.x + h1 * wv2.y;
                p3[mt][1][0] += h2 * wv0.x + h3 * wv0.y;
                p3[mt][1][1] += h2 * wv1.x + h3 * wv1.y;
                p3[mt][1][2] += h2 * wv2.x + h3 * wv2.y;
            }
        }

        // quad-reduce (full 32-col partial per row)
        #pragma unroll
        for (int mt = 0; mt < 2; mt++)
            #pragma unroll
            for (int rh = 0; rh < 2; rh++)
                #pragma unroll
                for (int f = 0; f < 3; f++) {
                    float v = p3[mt][rh][f];
                    v += __shfl_xor_sync(0xffffffffu, v, 1);
                    v += __shfl_xor_sync(0xffffffffu, v, 2);
                    p3[mt][rh][f] = v;
                }

        if ((lane & 3) == 0) {
            const int g = lane >> 2;
            #pragma unroll
            for (int mt = 0; mt < 2; mt++)
                #pragma unroll
                for (int rh = 0; rh < 2; rh++) {
                    int rowl = m2 * 32 + mt * 16 + rh * 8 + g;   // 0..63
                    #pragma unroll
                    for (int f = 0; f < 3; f++)
                        sm[PB_OFF + rowl * 12 + nb * 3 + f] = p3[mt][rh][f];
                }
        }
        __syncthreads();   // pbuf complete

        // ---- finalize: reduce 4 nb-partials, add b3, write outputs ----
        if (tid < 64) {
            long long g = (long long)c * 256 + qd * 64 + tid;
            const float* pb = &sm[PB_OFF + tid * 12];
            float pxv[3] = { px0, px1, px2 };
            #pragma unroll
            for (int f = 0; f < 3; f++) {
                float o = pb[f] + pb[3 + f] + pb[6 + f] + pb[9 + f] + __ldg(&b3[f]);
                out[g * 3 + f]        = pxv[f] + o;
                out[xoff + g * 3 + f] = o;
            }
        }
    }
}

extern "C" void kernel_launch(void* const* d_in, const int* in_sizes, int n_in,
                              void* d_out, int out_size) {
    const float* points    = (const float*)d_in[0];
    const float* enc       = (const float*)d_in[1];
    const float* W1        = (const float*)d_in[2];
    const float* b1        = (const float*)d_in[3];
    const float* W2        = (const float*)d_in[4];
    const float* b2        = (const float*)d_in[5];
    const float* W3        = (const float*)d_in[6];
    const float* b3        = (const float*)d_in[7];
    const int*   complexes = (const int*)d_in[8];   // JAX int64 -> int32 (x64 disabled)

    const int C = in_sizes[8] / 4;
    float* out = (float*)d_out;

    int grid = 2 * 148;                // persistent: 2 CTAs per SM on B200
    if (grid > 4 * C) grid = 4 * C;

    cudaFuncSetAttribute(nsc_sq_kernel,
                         cudaFuncAttributeMaxDynamicSharedMemorySize, SMEM_BYTES);
    nsc_sq_kernel<<<grid, 256, SMEM_BYTES>>>(points, enc, W1, b1, W2, b2, W3, b3,
                                             complexes, out, C,
                                             (long long)out_size - 1);
}